// round 2
// baseline (speedup 1.0000x reference)
#include <cuda_runtime.h>

// Problem constants (fixed shapes)
#define MB 32      // effective batch m = B*T = 4*8 (raw-reinterpret reshape)
#define CC 256     // channels
#define NN 1024    // pixels per map (32*32)
#define RR 320     // fused qkv rows: 32 q + 32 k + 256 v

// Scratch (module-load allocated; no cudaMalloc anywhere)
__device__ float g_qkv[MB * RR * NN];                 // 40 MB: rows 0-31 q, 32-63 k, 64-319 v
__device__ float g_attn[(size_t)MB * NN * NN];        // 134 MB: unnormalized exp(E)

// ---------------------------------------------------------------------------
// Kernel 1: fused QKV projection.  P = W'(320x256) @ X_m(256x1024) + b'
// Tile: 64 rows x 128 cols, BK=32, 256 threads, 4x8 microtile.
// ---------------------------------------------------------------------------
__global__ __launch_bounds__(256) void k_qkv(
    const float* __restrict__ x,
    const float* __restrict__ wq, const float* __restrict__ bq,
    const float* __restrict__ wk, const float* __restrict__ bk,
    const float* __restrict__ wv, const float* __restrict__ bv)
{
    const int m  = blockIdx.z;
    const int r0 = blockIdx.y * 64;
    const int n0 = blockIdx.x * 128;

    __shared__ float As[64][32];    // W' tile, row-major (broadcast scalar reads)
    __shared__ float Bs[32][128];   // X tile (vector reads)

    const int tid = threadIdx.x;
    const int tx  = tid & 15;       // 16 col-groups
    const int ty  = tid >> 4;       // 16 row-groups
    const float* xm = x + m * (CC * NN);

    float acc[4][8];
    #pragma unroll
    for (int i = 0; i < 4; i++)
        #pragma unroll
        for (int j = 0; j < 8; j++) acc[i][j] = 0.f;

    for (int k0 = 0; k0 < CC; k0 += 32) {
        // As[i][k] = W'[r0+i][k0+k]  (coalesced global, conflict-free STS)
        #pragma unroll
        for (int p = 0; p < 8; p++) {
            int l = tid + p * 256;
            int i = l >> 5;
            int k = l & 31;
            int r = r0 + i;
            float w;
            if (r < 32)      w = wq[r * CC + k0 + k];
            else if (r < 64) w = wk[(r - 32) * CC + k0 + k];
            else             w = wv[(r - 64) * CC + k0 + k];
            As[i][k] = w;
        }
        // Bs[k][j] = X[m][k0+k][n0+j]  (float4, fully coalesced)
        #pragma unroll
        for (int p = 0; p < 4; p++) {
            int f  = tid + p * 256;
            int k  = f >> 5;
            int c4 = f & 31;
            *(float4*)&Bs[k][c4 * 4] =
                *(const float4*)&xm[(k0 + k) * NN + n0 + c4 * 4];
        }
        __syncthreads();

        #pragma unroll
        for (int k = 0; k < 32; k++) {
            float a0 = As[ty * 4 + 0][k];
            float a1 = As[ty * 4 + 1][k];
            float a2 = As[ty * 4 + 2][k];
            float a3 = As[ty * 4 + 3][k];
            float4 b0 = *(const float4*)&Bs[k][tx * 4];
            float4 b1 = *(const float4*)&Bs[k][tx * 4 + 64];
            float b[8] = {b0.x, b0.y, b0.z, b0.w, b1.x, b1.y, b1.z, b1.w};
            float a[4] = {a0, a1, a2, a3};
            #pragma unroll
            for (int i = 0; i < 4; i++)
                #pragma unroll
                for (int j = 0; j < 8; j++)
                    acc[i][j] += a[i] * b[j];
        }
        __syncthreads();
    }

    #pragma unroll
    for (int i = 0; i < 4; i++) {
        int r = r0 + ty * 4 + i;
        float bb = (r < 32) ? bq[r] : ((r < 64) ? bk[r - 32] : bv[r - 64]);
        float* orow = g_qkv + (m * RR + r) * NN + n0;
        float4 v0, v1;
        v0.x = acc[i][0] + bb; v0.y = acc[i][1] + bb;
        v0.z = acc[i][2] + bb; v0.w = acc[i][3] + bb;
        v1.x = acc[i][4] + bb; v1.y = acc[i][5] + bb;
        v1.z = acc[i][6] + bb; v1.w = acc[i][7] + bb;
        *(float4*)&orow[tx * 4]      = v0;
        *(float4*)&orow[tx * 4 + 64] = v1;
    }
}

// ---------------------------------------------------------------------------
// Kernel 2: energy + unnormalized softmax, single pass.
// Block = 32 energy rows (n0..n0+31) of one batch.  e[n][j] = sum_o q[o][n]k[o][j]
// Writes exp(e) to g_attn; folds 1/rowsum into V columns in place (so K3 is a
// pure GEMM).  No max subtraction needed: |e| <~ 25 << 88.
// ---------------------------------------------------------------------------
__global__ __launch_bounds__(256) void k_attn()
{
    const int m  = blockIdx.y;
    const int n0 = blockIdx.x * 32;

    __shared__ float Qs[32][32];    // [o][r]
    __shared__ float Ks[32][128];   // [o][j]
    __shared__ float izs[32];

    const int tid = threadIdx.x;
    const int r   = tid >> 3;       // 0..31 (energy row within tile)
    const int c8  = tid & 7;        // 0..7  (col lane)

    const float* qbase = g_qkv + m * RR * NN;          // q rows
    const float* kbase = qbase + 32 * NN;              // k rows
    float* am = g_attn + (size_t)m * NN * NN;

    #pragma unroll
    for (int p = 0; p < 4; p++) {
        int l  = tid + p * 256;
        int o  = l >> 5;
        int rr = l & 31;
        Qs[o][rr] = qbase[o * NN + n0 + rr];
    }

    float ssum = 0.f;
    for (int j0 = 0; j0 < NN; j0 += 128) {
        __syncthreads();
        #pragma unroll
        for (int p = 0; p < 4; p++) {
            int f  = tid + p * 256;
            int o  = f >> 5;
            int c4 = f & 31;
            *(float4*)&Ks[o][c4 * 4] =
                *(const float4*)&kbase[o * NN + j0 + c4 * 4];
        }
        __syncthreads();

        float e[16];
        #pragma unroll
        for (int i = 0; i < 16; i++) e[i] = 0.f;
        #pragma unroll
        for (int o = 0; o < 32; o++) {
            float qv = Qs[o][r];
            #pragma unroll
            for (int q = 0; q < 4; q++) {
                float4 kv = *(const float4*)&Ks[o][c8 * 4 + q * 32];
                e[q * 4 + 0] += qv * kv.x;
                e[q * 4 + 1] += qv * kv.y;
                e[q * 4 + 2] += qv * kv.z;
                e[q * 4 + 3] += qv * kv.w;
            }
        }

        float* arow = am + (n0 + r) * NN + j0;
        #pragma unroll
        for (int q = 0; q < 4; q++) {
            float4 ev;
            ev.x = __expf(e[q * 4 + 0]);
            ev.y = __expf(e[q * 4 + 1]);
            ev.z = __expf(e[q * 4 + 2]);
            ev.w = __expf(e[q * 4 + 3]);
            ssum += (ev.x + ev.y) + (ev.z + ev.w);
            *(float4*)&arow[c8 * 4 + q * 32] = ev;
        }
    }

    // reduce row sum across the 8 lanes of this row (lanes stay in-warp)
    ssum += __shfl_xor_sync(0xffffffffu, ssum, 1);
    ssum += __shfl_xor_sync(0xffffffffu, ssum, 2);
    ssum += __shfl_xor_sync(0xffffffffu, ssum, 4);
    float iz = 1.0f / ssum;
    if (c8 == 0) izs[r] = iz;
    __syncthreads();

    // scale V columns [n0, n0+32) by invZ in place (256 rows x 32 cols)
    float* vm = g_qkv + (m * RR + 64) * NN;
    #pragma unroll
    for (int p = 0; p < 32; p++) {
        int l   = tid + p * 256;
        int c   = l >> 5;
        int col = l & 31;
        vm[c * NN + n0 + col] *= izs[col];
    }
}

// ---------------------------------------------------------------------------
// Kernel 3: out = gamma * (V' @ P) + x.
// Tile: 128x128, BK=32, 256 threads, 8x8 microtile.
// ---------------------------------------------------------------------------
__global__ __launch_bounds__(256) void k_out(
    const float* __restrict__ x, const float* __restrict__ gp,
    float* __restrict__ out)
{
    const int m  = blockIdx.z;
    const int c0 = blockIdx.y * 128;
    const int j0 = blockIdx.x * 128;

    __shared__ float Vs[128][32];   // V' tile row-major (broadcast scalar reads)
    __shared__ float Bs[32][128];   // P tile (vector reads)

    const int tid = threadIdx.x;
    const int tx  = tid & 15;
    const int ty  = tid >> 4;

    const float* vm = g_qkv + (m * RR + 64) * NN;
    const float* am = g_attn + (size_t)m * NN * NN;

    float acc[8][8];
    #pragma unroll
    for (int i = 0; i < 8; i++)
        #pragma unroll
        for (int j = 0; j < 8; j++) acc[i][j] = 0.f;

    for (int k0 = 0; k0 < NN; k0 += 32) {
        #pragma unroll
        for (int p = 0; p < 16; p++) {
            int l = tid + p * 256;
            int i = l >> 5;
            int k = l & 31;
            Vs[i][k] = vm[(c0 + i) * NN + k0 + k];
        }
        #pragma unroll
        for (int p = 0; p < 4; p++) {
            int f  = tid + p * 256;
            int k  = f >> 5;
            int c4 = f & 31;
            *(float4*)&Bs[k][c4 * 4] =
                *(const float4*)&am[(k0 + k) * NN + j0 + c4 * 4];
        }
        __syncthreads();

        #pragma unroll
        for (int k = 0; k < 32; k++) {
            float a[8];
            #pragma unroll
            for (int i = 0; i < 8; i++) a[i] = Vs[ty * 8 + i][k];
            float4 b0 = *(const float4*)&Bs[k][tx * 4];
            float4 b1 = *(const float4*)&Bs[k][tx * 4 + 64];
            float b[8] = {b0.x, b0.y, b0.z, b0.w, b1.x, b1.y, b1.z, b1.w};
            #pragma unroll
            for (int i = 0; i < 8; i++)
                #pragma unroll
                for (int j = 0; j < 8; j++)
                    acc[i][j] += a[i] * b[j];
        }
        __syncthreads();
    }

    const float g = *gp;
    const float* xm = x + m * (CC * NN);
    float* om = out + m * (CC * NN);
    #pragma unroll
    for (int i = 0; i < 8; i++) {
        int c = c0 + ty * 8 + i;
        const float* xrow = xm + c * NN + j0;
        float* orow = om + c * NN + j0;
        float4 x0 = *(const float4*)&xrow[tx * 4];
        float4 x1 = *(const float4*)&xrow[tx * 4 + 64];
        float4 o0, o1;
        o0.x = g * acc[i][0] + x0.x; o0.y = g * acc[i][1] + x0.y;
        o0.z = g * acc[i][2] + x0.z; o0.w = g * acc[i][3] + x0.w;
        o1.x = g * acc[i][4] + x1.x; o1.y = g * acc[i][5] + x1.y;
        o1.z = g * acc[i][6] + x1.z; o1.w = g * acc[i][7] + x1.w;
        *(float4*)&orow[tx * 4]      = o0;
        *(float4*)&orow[tx * 4 + 64] = o1;
    }
}

// ---------------------------------------------------------------------------
extern "C" void kernel_launch(void* const* d_in, const int* in_sizes, int n_in,
                              void* d_out, int out_size)
{
    const float* x     = (const float*)d_in[0];
    const float* wq    = (const float*)d_in[1];
    const float* bq    = (const float*)d_in[2];
    const float* wk    = (const float*)d_in[3];
    const float* bk    = (const float*)d_in[4];
    const float* wv    = (const float*)d_in[5];
    const float* bv    = (const float*)d_in[6];
    const float* gamma = (const float*)d_in[7];
    float* out = (float*)d_out;

    dim3 g1(NN / 128, RR / 64, MB);   // 8 x 5 x 32
    k_qkv<<<g1, 256>>>(x, wq, bq, wk, bk, wv, bv);

    dim3 g2(NN / 32, MB);             // 32 x 32
    k_attn<<<g2, 256>>>();

    dim3 g3(NN / 128, CC / 128, MB);  // 8 x 2 x 32
    k_out<<<g3, 256>>>(x, gamma, out);
}

// round 3
// speedup vs baseline: 1.0242x; 1.0242x over previous
#include <cuda_runtime.h>

// Problem constants (fixed shapes)
#define MB 32      // effective batch m = B*T = 4*8 (raw-reinterpret reshape)
#define CC 256     // channels
#define NN 1024    // pixels per map (32*32)
#define RR 320     // fused qkv rows: 32 q + 32 k + 256 v

typedef unsigned long long u64;

// Scratch (module-load allocated; no cudaMalloc anywhere)
__device__ float g_qkv[MB * RR * NN];                 // 40 MB: rows 0-31 q, 32-63 k, 64-319 v
__device__ float g_attn[(size_t)MB * NN * NN];        // 134 MB: unnormalized exp(E)

// ---- packed fp32x2 helpers (FFMA2: 2 FMAs per issue; PTX-only path) -------
__device__ __forceinline__ u64 pack2(float lo, float hi) {
    u64 r; asm("mov.b64 %0,{%1,%2};" : "=l"(r) : "f"(lo), "f"(hi)); return r;
}
__device__ __forceinline__ u64 ffma2(u64 a, u64 b, u64 c) {
    u64 d; asm("fma.rn.f32x2 %0,%1,%2,%3;" : "=l"(d) : "l"(a), "l"(b), "l"(c));
    return d;
}
__device__ __forceinline__ float2 unpack2(u64 v) {
    float2 f; asm("mov.b64 {%0,%1},%2;" : "=f"(f.x), "=f"(f.y) : "l"(v));
    return f;
}

// ---------------------------------------------------------------------------
// Kernel 1: fused QKV projection.  P = W'(320x256) @ X_m(256x1024) + b'
// Tile: 64 rows x 128 cols, BK=32, 256 threads, 4x8 microtile (2 row-pairs).
// A tile stored k-major transposed (AsT[k][r], width 66 => 2-way STS, aligned
// LDS.64 row-pair loads).
// ---------------------------------------------------------------------------
__global__ __launch_bounds__(256) void k_qkv(
    const float* __restrict__ x,
    const float* __restrict__ wq, const float* __restrict__ bq,
    const float* __restrict__ wk, const float* __restrict__ bk,
    const float* __restrict__ wv, const float* __restrict__ bv)
{
    const int m  = blockIdx.z;
    const int r0 = blockIdx.y * 64;
    const int n0 = blockIdx.x * 128;

    __shared__ float AsT[32 * 66];   // [k][r] transposed, padded
    __shared__ float Bs[32][128];    // X tile

    const int tid = threadIdx.x;
    const int tx  = tid & 15;
    const int ty  = tid >> 4;
    const float* xm = x + m * (CC * NN);

    u64 acc2[2][8];                  // row-pairs (ty*4+2ip+{0,1}) x 8 cols
    #pragma unroll
    for (int i = 0; i < 2; i++)
        #pragma unroll
        for (int j = 0; j < 8; j++) acc2[i][j] = 0ull;

    for (int k0 = 0; k0 < CC; k0 += 32) {
        #pragma unroll
        for (int p = 0; p < 8; p++) {
            int l = tid + p * 256;
            int i = l >> 5;          // row within tile (fixed per warp)
            int k = l & 31;          // k = lane (coalesced LDG)
            int r = r0 + i;
            float w;
            if (r < 32)      w = wq[r * CC + k0 + k];
            else if (r < 64) w = wk[(r - 32) * CC + k0 + k];
            else             w = wv[(r - 64) * CC + k0 + k];
            AsT[k * 66 + i] = w;
        }
        #pragma unroll
        for (int p = 0; p < 4; p++) {
            int f  = tid + p * 256;
            int k  = f >> 5;
            int c4 = f & 31;
            *(float4*)&Bs[k][c4 * 4] =
                *(const float4*)&xm[(k0 + k) * NN + n0 + c4 * 4];
        }
        __syncthreads();

        #pragma unroll
        for (int k = 0; k < 32; k++) {
            const u64* arow = (const u64*)&AsT[k * 66 + ty * 4];
            u64 a0 = arow[0];
            u64 a1 = arow[1];
            float4 b0 = *(const float4*)&Bs[k][tx * 4];
            float4 b1 = *(const float4*)&Bs[k][tx * 4 + 64];
            u64 bd[8];
            bd[0] = pack2(b0.x, b0.x); bd[1] = pack2(b0.y, b0.y);
            bd[2] = pack2(b0.z, b0.z); bd[3] = pack2(b0.w, b0.w);
            bd[4] = pack2(b1.x, b1.x); bd[5] = pack2(b1.y, b1.y);
            bd[6] = pack2(b1.z, b1.z); bd[7] = pack2(b1.w, b1.w);
            #pragma unroll
            for (int j = 0; j < 8; j++) {
                acc2[0][j] = ffma2(a0, bd[j], acc2[0][j]);
                acc2[1][j] = ffma2(a1, bd[j], acc2[1][j]);
            }
        }
        __syncthreads();
    }

    #pragma unroll
    for (int ip = 0; ip < 2; ip++) {
        float2 f[8];
        #pragma unroll
        for (int j = 0; j < 8; j++) f[j] = unpack2(acc2[ip][j]);
        #pragma unroll
        for (int h = 0; h < 2; h++) {
            int r = r0 + ty * 4 + 2 * ip + h;
            float bb = (r < 32) ? bq[r] : ((r < 64) ? bk[r - 32] : bv[r - 64]);
            float* orow = g_qkv + (m * RR + r) * NN + n0;
            float4 v0, v1;
            v0.x = (h ? f[0].y : f[0].x) + bb;
            v0.y = (h ? f[1].y : f[1].x) + bb;
            v0.z = (h ? f[2].y : f[2].x) + bb;
            v0.w = (h ? f[3].y : f[3].x) + bb;
            v1.x = (h ? f[4].y : f[4].x) + bb;
            v1.y = (h ? f[5].y : f[5].x) + bb;
            v1.z = (h ? f[6].y : f[6].x) + bb;
            v1.w = (h ? f[7].y : f[7].x) + bb;
            *(float4*)&orow[tx * 4]      = v0;
            *(float4*)&orow[tx * 4 + 64] = v1;
        }
    }
}

// ---------------------------------------------------------------------------
// Kernel 2: energy + unnormalized softmax, single pass (packed f32x2 dots).
// Block = 32 energy rows of one batch. Writes exp(E) to g_attn; folds 1/rowsum
// into V columns in place. No max subtraction needed: |e| <~ 25 << 88.
// ---------------------------------------------------------------------------
__global__ __launch_bounds__(256) void k_attn()
{
    const int m  = blockIdx.y;
    const int n0 = blockIdx.x * 32;

    __shared__ float Qs[32][32];    // [o][r]
    __shared__ float Ks[32][128];   // [o][j]
    __shared__ float izs[32];

    const int tid = threadIdx.x;
    const int r   = tid >> 3;       // 0..31 (energy row within tile)
    const int c8  = tid & 7;        // 0..7  (col lane)

    const float* qbase = g_qkv + m * RR * NN;          // q rows
    const float* kbase = qbase + 32 * NN;              // k rows
    float* am = g_attn + (size_t)m * NN * NN;

    #pragma unroll
    for (int p = 0; p < 4; p++) {
        int l  = tid + p * 256;
        int o  = l >> 5;
        int rr = l & 31;
        Qs[o][rr] = qbase[o * NN + n0 + rr];
    }

    float ssum = 0.f;
    for (int j0 = 0; j0 < NN; j0 += 128) {
        __syncthreads();
        #pragma unroll
        for (int p = 0; p < 4; p++) {
            int f  = tid + p * 256;
            int o  = f >> 5;
            int c4 = f & 31;
            *(float4*)&Ks[o][c4 * 4] =
                *(const float4*)&kbase[o * NN + j0 + c4 * 4];
        }
        __syncthreads();

        u64 e2[8];
        #pragma unroll
        for (int i = 0; i < 8; i++) e2[i] = 0ull;
        #pragma unroll
        for (int o = 0; o < 32; o++) {
            float qv = Qs[o][r];
            u64 qd = pack2(qv, qv);
            #pragma unroll
            for (int q = 0; q < 4; q++) {
                ulonglong2 kv = *(const ulonglong2*)&Ks[o][c8 * 4 + q * 32];
                e2[q * 2 + 0] = ffma2(qd, kv.x, e2[q * 2 + 0]);
                e2[q * 2 + 1] = ffma2(qd, kv.y, e2[q * 2 + 1]);
            }
        }

        float* arow = am + (n0 + r) * NN + j0;
        #pragma unroll
        for (int q = 0; q < 4; q++) {
            float2 lo = unpack2(e2[q * 2 + 0]);
            float2 hi = unpack2(e2[q * 2 + 1]);
            float4 ev;
            ev.x = __expf(lo.x);
            ev.y = __expf(lo.y);
            ev.z = __expf(hi.x);
            ev.w = __expf(hi.y);
            ssum += (ev.x + ev.y) + (ev.z + ev.w);
            *(float4*)&arow[c8 * 4 + q * 32] = ev;
        }
    }

    // reduce row sum across the 8 lanes of this row (lanes stay in-warp)
    ssum += __shfl_xor_sync(0xffffffffu, ssum, 1);
    ssum += __shfl_xor_sync(0xffffffffu, ssum, 2);
    ssum += __shfl_xor_sync(0xffffffffu, ssum, 4);
    float iz = 1.0f / ssum;
    if (c8 == 0) izs[r] = iz;
    __syncthreads();

    // scale V columns [n0, n0+32) by invZ in place (256 rows x 32 cols)
    float* vm = g_qkv + (m * RR + 64) * NN;
    #pragma unroll
    for (int p = 0; p < 32; p++) {
        int l   = tid + p * 256;
        int c   = l >> 5;
        int col = l & 31;
        vm[c * NN + n0 + col] *= izs[col];
    }
}

// ---------------------------------------------------------------------------
// Kernel 3: out = gamma * (V' @ P) + x.
// Tile: 128x128, BK=32, 256 threads, 8x8 microtile as 4 row-pairs x 8 cols.
// V tile stored k-major transposed (Vst[k][i], width 130) so row-pair loads
// are natural 64-bit LDS; B scalars duplicated via mov.b64.
// ---------------------------------------------------------------------------
__global__ __launch_bounds__(256) void k_out(
    const float* __restrict__ x, const float* __restrict__ gp,
    float* __restrict__ out)
{
    const int m  = blockIdx.z;
    const int c0 = blockIdx.y * 128;
    const int j0 = blockIdx.x * 128;

    __shared__ float Vst[32 * 130];  // [k][i] transposed, padded (2-way STS)
    __shared__ float Bs[32][128];    // P tile

    const int tid = threadIdx.x;
    const int tx  = tid & 15;
    const int ty  = tid >> 4;

    const float* vm = g_qkv + (m * RR + 64) * NN;
    const float* am = g_attn + (size_t)m * NN * NN;

    u64 acc2[4][8];                  // 4 row-pairs x 8 cols = 8x8 floats
    #pragma unroll
    for (int i = 0; i < 4; i++)
        #pragma unroll
        for (int j = 0; j < 8; j++) acc2[i][j] = 0ull;

    for (int k0 = 0; k0 < NN; k0 += 32) {
        #pragma unroll
        for (int p = 0; p < 16; p++) {
            int l = tid + p * 256;
            int i = l >> 5;          // row (fixed per warp)
            int k = l & 31;          // k = lane (coalesced LDG)
            Vst[k * 130 + i] = vm[(c0 + i) * NN + k0 + k];
        }
        #pragma unroll
        for (int p = 0; p < 4; p++) {
            int f  = tid + p * 256;
            int k  = f >> 5;
            int c4 = f & 31;
            *(float4*)&Bs[k][c4 * 4] =
                *(const float4*)&am[(k0 + k) * NN + j0 + c4 * 4];
        }
        __syncthreads();

        #pragma unroll
        for (int k = 0; k < 32; k++) {
            const u64* arow = (const u64*)&Vst[k * 130 + ty * 8];
            u64 a0 = arow[0];
            u64 a1 = arow[1];
            u64 a2 = arow[2];
            u64 a3 = arow[3];
            float4 b0 = *(const float4*)&Bs[k][tx * 4];
            float4 b1 = *(const float4*)&Bs[k][tx * 4 + 64];
            u64 bd[8];
            bd[0] = pack2(b0.x, b0.x); bd[1] = pack2(b0.y, b0.y);
            bd[2] = pack2(b0.z, b0.z); bd[3] = pack2(b0.w, b0.w);
            bd[4] = pack2(b1.x, b1.x); bd[5] = pack2(b1.y, b1.y);
            bd[6] = pack2(b1.z, b1.z); bd[7] = pack2(b1.w, b1.w);
            #pragma unroll
            for (int j = 0; j < 8; j++) {
                acc2[0][j] = ffma2(a0, bd[j], acc2[0][j]);
                acc2[1][j] = ffma2(a1, bd[j], acc2[1][j]);
                acc2[2][j] = ffma2(a2, bd[j], acc2[2][j]);
                acc2[3][j] = ffma2(a3, bd[j], acc2[3][j]);
            }
        }
        __syncthreads();
    }

    const float g = *gp;
    const float* xm = x + m * (CC * NN);
    float* om = out + m * (CC * NN);
    #pragma unroll
    for (int ip = 0; ip < 4; ip++) {
        float2 f[8];
        #pragma unroll
        for (int j = 0; j < 8; j++) f[j] = unpack2(acc2[ip][j]);
        #pragma unroll
        for (int h = 0; h < 2; h++) {
            int c = c0 + ty * 8 + 2 * ip + h;
            const float* xrow = xm + c * NN + j0;
            float* orow = om + c * NN + j0;
            float4 x0 = *(const float4*)&xrow[tx * 4];
            float4 x1 = *(const float4*)&xrow[tx * 4 + 64];
            float4 o0, o1;
            o0.x = g * (h ? f[0].y : f[0].x) + x0.x;
            o0.y = g * (h ? f[1].y : f[1].x) + x0.y;
            o0.z = g * (h ? f[2].y : f[2].x) + x0.z;
            o0.w = g * (h ? f[3].y : f[3].x) + x0.w;
            o1.x = g * (h ? f[4].y : f[4].x) + x1.x;
            o1.y = g * (h ? f[5].y : f[5].x) + x1.y;
            o1.z = g * (h ? f[6].y : f[6].x) + x1.z;
            o1.w = g * (h ? f[7].y : f[7].x) + x1.w;
            *(float4*)&orow[tx * 4]      = o0;
            *(float4*)&orow[tx * 4 + 64] = o1;
        }
    }
}

// ---------------------------------------------------------------------------
extern "C" void kernel_launch(void* const* d_in, const int* in_sizes, int n_in,
                              void* d_out, int out_size)
{
    const float* x     = (const float*)d_in[0];
    const float* wq    = (const float*)d_in[1];
    const float* bq    = (const float*)d_in[2];
    const float* wk    = (const float*)d_in[3];
    const float* bk    = (const float*)d_in[4];
    const float* wv    = (const float*)d_in[5];
    const float* bv    = (const float*)d_in[6];
    const float* gamma = (const float*)d_in[7];
    float* out = (float*)d_out;

    dim3 g1(NN / 128, RR / 64, MB);   // 8 x 5 x 32
    k_qkv<<<g1, 256>>>(x, wq, bq, wk, bk, wv, bv);

    dim3 g2(NN / 32, MB);             // 32 x 32
    k_attn<<<g2, 256>>>();

    dim3 g3(NN / 128, CC / 128, MB);  // 8 x 2 x 32
    k_out<<<g3, 256>>>(x, gamma, out);
}

// round 5
// speedup vs baseline: 1.2384x; 1.2091x over previous
#include <cuda_runtime.h>
#include <cstdint>
#include <mma.h>

using namespace nvcuda;

// Problem constants (fixed shapes)
#define MB 32      // effective batch m = B*T (raw-reinterpret reshape)
#define CC 256     // channels
#define NN 1024    // pixels per map (32*32)
#define RR 320     // fused qkv rows: 32 q + 32 k + 256 v

typedef unsigned long long u64;

// Scratch (module-load allocated; no cudaMalloc anywhere)
__device__ float g_qkv[MB * RR * NN];                 // 40 MB
__device__ float g_attn[(size_t)MB * NN * NN];        // 134 MB: unnormalized exp(E)

// ---- packed fp32x2 helpers -------------------------------------------------
__device__ __forceinline__ u64 pack2(float lo, float hi) {
    u64 r; asm("mov.b64 %0,{%1,%2};" : "=l"(r) : "f"(lo), "f"(hi)); return r;
}
__device__ __forceinline__ u64 ffma2(u64 a, u64 b, u64 c) {
    u64 d; asm("fma.rn.f32x2 %0,%1,%2,%3;" : "=l"(d) : "l"(a), "l"(b), "l"(c));
    return d;
}
__device__ __forceinline__ float2 unpack2(u64 v) {
    float2 f; asm("mov.b64 {%0,%1},%2;" : "=f"(f.x), "=f"(f.y) : "l"(v));
    return f;
}

// ---------------------------------------------------------------------------
// Kernel 1: fused QKV projection (FFMA2 path; exact fp32)
// ---------------------------------------------------------------------------
__global__ __launch_bounds__(256) void k_qkv(
    const float* __restrict__ x,
    const float* __restrict__ wq, const float* __restrict__ bq,
    const float* __restrict__ wk, const float* __restrict__ bk,
    const float* __restrict__ wv, const float* __restrict__ bv)
{
    const int m  = blockIdx.z;
    const int r0 = blockIdx.y * 64;
    const int n0 = blockIdx.x * 128;

    __shared__ float AsT[32 * 66];
    __shared__ float Bs[32][128];

    const int tid = threadIdx.x;
    const int tx  = tid & 15;
    const int ty  = tid >> 4;
    const float* xm = x + m * (CC * NN);

    u64 acc2[2][8];
    #pragma unroll
    for (int i = 0; i < 2; i++)
        #pragma unroll
        for (int j = 0; j < 8; j++) acc2[i][j] = 0ull;

    for (int k0 = 0; k0 < CC; k0 += 32) {
        #pragma unroll
        for (int p = 0; p < 8; p++) {
            int l = tid + p * 256;
            int i = l >> 5;
            int k = l & 31;
            int r = r0 + i;
            float w;
            if (r < 32)      w = wq[r * CC + k0 + k];
            else if (r < 64) w = wk[(r - 32) * CC + k0 + k];
            else             w = wv[(r - 64) * CC + k0 + k];
            AsT[k * 66 + i] = w;
        }
        #pragma unroll
        for (int p = 0; p < 4; p++) {
            int f  = tid + p * 256;
            int k  = f >> 5;
            int c4 = f & 31;
            *(float4*)&Bs[k][c4 * 4] =
                *(const float4*)&xm[(k0 + k) * NN + n0 + c4 * 4];
        }
        __syncthreads();

        #pragma unroll
        for (int k = 0; k < 32; k++) {
            const u64* arow = (const u64*)&AsT[k * 66 + ty * 4];
            u64 a0 = arow[0];
            u64 a1 = arow[1];
            float4 b0 = *(const float4*)&Bs[k][tx * 4];
            float4 b1 = *(const float4*)&Bs[k][tx * 4 + 64];
            u64 bd[8];
            bd[0] = pack2(b0.x, b0.x); bd[1] = pack2(b0.y, b0.y);
            bd[2] = pack2(b0.z, b0.z); bd[3] = pack2(b0.w, b0.w);
            bd[4] = pack2(b1.x, b1.x); bd[5] = pack2(b1.y, b1.y);
            bd[6] = pack2(b1.z, b1.z); bd[7] = pack2(b1.w, b1.w);
            #pragma unroll
            for (int j = 0; j < 8; j++) {
                acc2[0][j] = ffma2(a0, bd[j], acc2[0][j]);
                acc2[1][j] = ffma2(a1, bd[j], acc2[1][j]);
            }
        }
        __syncthreads();
    }

    #pragma unroll
    for (int ip = 0; ip < 2; ip++) {
        float2 f[8];
        #pragma unroll
        for (int j = 0; j < 8; j++) f[j] = unpack2(acc2[ip][j]);
        #pragma unroll
        for (int h = 0; h < 2; h++) {
            int r = r0 + ty * 4 + 2 * ip + h;
            float bb = (r < 32) ? bq[r] : ((r < 64) ? bk[r - 32] : bv[r - 64]);
            float* orow = g_qkv + (m * RR + r) * NN + n0;
            float4 v0, v1;
            v0.x = (h ? f[0].y : f[0].x) + bb;
            v0.y = (h ? f[1].y : f[1].x) + bb;
            v0.z = (h ? f[2].y : f[2].x) + bb;
            v0.w = (h ? f[3].y : f[3].x) + bb;
            v1.x = (h ? f[4].y : f[4].x) + bb;
            v1.y = (h ? f[5].y : f[5].x) + bb;
            v1.z = (h ? f[6].y : f[6].x) + bb;
            v1.w = (h ? f[7].y : f[7].x) + bb;
            *(float4*)&orow[tx * 4]      = v0;
            *(float4*)&orow[tx * 4 + 64] = v1;
        }
    }
}

// ---------------------------------------------------------------------------
// Kernel 2: energy + unnormalized softmax, single pass (exact fp32)
// ---------------------------------------------------------------------------
__global__ __launch_bounds__(256) void k_attn()
{
    const int m  = blockIdx.y;
    const int n0 = blockIdx.x * 32;

    __shared__ float Qs[32][32];
    __shared__ float Ks[32][128];
    __shared__ float izs[32];

    const int tid = threadIdx.x;
    const int r   = tid >> 3;
    const int c8  = tid & 7;

    const float* qbase = g_qkv + m * RR * NN;
    const float* kbase = qbase + 32 * NN;
    float* am = g_attn + (size_t)m * NN * NN;

    #pragma unroll
    for (int p = 0; p < 4; p++) {
        int l  = tid + p * 256;
        int o  = l >> 5;
        int rr = l & 31;
        Qs[o][rr] = qbase[o * NN + n0 + rr];
    }

    float ssum = 0.f;
    for (int j0 = 0; j0 < NN; j0 += 128) {
        __syncthreads();
        #pragma unroll
        for (int p = 0; p < 4; p++) {
            int f  = tid + p * 256;
            int o  = f >> 5;
            int c4 = f & 31;
            *(float4*)&Ks[o][c4 * 4] =
                *(const float4*)&kbase[o * NN + j0 + c4 * 4];
        }
        __syncthreads();

        u64 e2[8];
        #pragma unroll
        for (int i = 0; i < 8; i++) e2[i] = 0ull;
        #pragma unroll
        for (int o = 0; o < 32; o++) {
            float qv = Qs[o][r];
            u64 qd = pack2(qv, qv);
            #pragma unroll
            for (int q = 0; q < 4; q++) {
                ulonglong2 kv = *(const ulonglong2*)&Ks[o][c8 * 4 + q * 32];
                e2[q * 2 + 0] = ffma2(qd, kv.x, e2[q * 2 + 0]);
                e2[q * 2 + 1] = ffma2(qd, kv.y, e2[q * 2 + 1]);
            }
        }

        float* arow = am + (n0 + r) * NN + j0;
        #pragma unroll
        for (int q = 0; q < 4; q++) {
            float2 lo = unpack2(e2[q * 2 + 0]);
            float2 hi = unpack2(e2[q * 2 + 1]);
            float4 ev;
            ev.x = __expf(lo.x);
            ev.y = __expf(lo.y);
            ev.z = __expf(hi.x);
            ev.w = __expf(hi.y);
            ssum += (ev.x + ev.y) + (ev.z + ev.w);
            *(float4*)&arow[c8 * 4 + q * 32] = ev;
        }
    }

    ssum += __shfl_xor_sync(0xffffffffu, ssum, 1);
    ssum += __shfl_xor_sync(0xffffffffu, ssum, 2);
    ssum += __shfl_xor_sync(0xffffffffu, ssum, 4);
    float iz = 1.0f / ssum;
    if (c8 == 0) izs[r] = iz;
    __syncthreads();

    float* vm = g_qkv + (m * RR + 64) * NN;
    #pragma unroll
    for (int p = 0; p < 32; p++) {
        int l   = tid + p * 256;
        int c   = l >> 5;
        int col = l & 31;
        vm[c * NN + n0 + col] *= izs[col];
    }
}

// ---------------------------------------------------------------------------
// Kernel 3: out = gamma * (V' @ exp(E)) + x  via wmma tf32 (arch-neutral HMMA).
// Block tile 128x128, BK=32; 8 warps as 2(M)x4(N); warp tile 64x32 = 4x2 frags
// of m16n16k8. B (exp(E)) is consumed row-major -> no transpose, coalesced.
// ---------------------------------------------------------------------------
#define A_LD 40            // 128 x 40 floats
#define B_LD 136           // 32 x 136 floats
#define AS_FLOATS (128 * A_LD)          // 5120
#define SCR_LD 36                        // epilogue scratch row stride
#define SMEM_K3 73728                    // max(37888 tiles, 8*64*36*4 scratch)

__global__ __launch_bounds__(256) void k_out_wmma(
    const float* __restrict__ x, const float* __restrict__ gp,
    float* __restrict__ out)
{
    extern __shared__ __align__(16) float smf[];
    float* As = smf;                 // [128][A_LD]
    float* Bs = smf + AS_FLOATS;     // [32][B_LD]

    const int m  = blockIdx.z;
    const int c0 = blockIdx.y * 128;
    const int j0 = blockIdx.x * 128;

    const int tid = threadIdx.x;
    const int wid = tid >> 5;
    const int lid = tid & 31;
    const int wy  = wid >> 2;        // 0..1  (M dir, 64 rows each)
    const int wx  = wid & 3;         // 0..3  (N dir, 32 cols each)

    const float* vm = g_qkv + (m * RR + 64) * NN;
    const float* am = g_attn + (size_t)m * NN * NN;

    wmma::fragment<wmma::accumulator, 16, 16, 8, float> acc[4][2];
    #pragma unroll
    for (int i = 0; i < 4; i++)
        #pragma unroll
        for (int j = 0; j < 2; j++) wmma::fill_fragment(acc[i][j], 0.0f);

    for (int k0 = 0; k0 < NN; k0 += 32) {
        // A tile: V'[c0..+128][k0..+32], tf32-rounded at STS
        #pragma unroll
        for (int p = 0; p < 4; p++) {
            int idx = tid + p * 256;
            int i   = idx >> 3;
            int c4  = idx & 7;
            float4 v = *(const float4*)&vm[(c0 + i) * NN + k0 + c4 * 4];
            v.x = wmma::__float_to_tf32(v.x);
            v.y = wmma::__float_to_tf32(v.y);
            v.z = wmma::__float_to_tf32(v.z);
            v.w = wmma::__float_to_tf32(v.w);
            *(float4*)&As[i * A_LD + c4 * 4] = v;
        }
        // B tile: exp(E)[k0..+32][j0..+128] straight copy (row-major)
        #pragma unroll
        for (int p = 0; p < 4; p++) {
            int idx = tid + p * 256;
            int k   = idx >> 5;
            int c4  = idx & 31;
            float4 b = *(const float4*)&am[(size_t)(k0 + k) * NN + j0 + c4 * 4];
            b.x = wmma::__float_to_tf32(b.x);
            b.y = wmma::__float_to_tf32(b.y);
            b.z = wmma::__float_to_tf32(b.z);
            b.w = wmma::__float_to_tf32(b.w);
            *(float4*)&Bs[k * B_LD + c4 * 4] = b;
        }
        __syncthreads();

        #pragma unroll
        for (int kk = 0; kk < 4; kk++) {
            wmma::fragment<wmma::matrix_a, 16, 16, 8, wmma::precision::tf32,
                           wmma::row_major> af[4];
            wmma::fragment<wmma::matrix_b, 16, 16, 8, wmma::precision::tf32,
                           wmma::row_major> bf[2];
            #pragma unroll
            for (int i = 0; i < 4; i++)
                wmma::load_matrix_sync(af[i],
                    &As[(wy * 64 + i * 16) * A_LD + kk * 8], A_LD);
            #pragma unroll
            for (int j = 0; j < 2; j++)
                wmma::load_matrix_sync(bf[j],
                    &Bs[kk * 8 * B_LD + wx * 32 + j * 16], B_LD);
            #pragma unroll
            for (int i = 0; i < 4; i++)
                #pragma unroll
                for (int j = 0; j < 2; j++)
                    wmma::mma_sync(acc[i][j], af[i], bf[j], acc[i][j]);
        }
        __syncthreads();
    }

    // ---- epilogue: frags -> smem scratch -> gamma*acc + x -> gmem ----
    float* ws = smf + wid * (64 * SCR_LD);
    #pragma unroll
    for (int i = 0; i < 4; i++)
        #pragma unroll
        for (int j = 0; j < 2; j++)
            wmma::store_matrix_sync(&ws[(i * 16) * SCR_LD + j * 16],
                                    acc[i][j], SCR_LD, wmma::mem_row_major);
    __syncwarp();

    const float g = *gp;
    const int rbase = c0 + wy * 64;
    const int cbase = j0 + wx * 32;
    const float* xm = x + (size_t)m * CC * NN;
    float* om = out + (size_t)m * CC * NN;
    #pragma unroll
    for (int it = 0; it < 16; it++) {
        int r  = it * 4 + (lid >> 3);
        int c4 = lid & 7;
        float4 a  = *(const float4*)&ws[r * SCR_LD + c4 * 4];
        const float* xrow = xm + (size_t)(rbase + r) * NN + cbase;
        float4 xv = *(const float4*)&xrow[c4 * 4];
        float4 o;
        o.x = g * a.x + xv.x;
        o.y = g * a.y + xv.y;
        o.z = g * a.z + xv.z;
        o.w = g * a.w + xv.w;
        *(float4*)&om[(size_t)(rbase + r) * NN + cbase + c4 * 4] = o;
    }
}

// ---------------------------------------------------------------------------
extern "C" void kernel_launch(void* const* d_in, const int* in_sizes, int n_in,
                              void* d_out, int out_size)
{
    const float* x     = (const float*)d_in[0];
    const float* wq    = (const float*)d_in[1];
    const float* bq    = (const float*)d_in[2];
    const float* wk    = (const float*)d_in[3];
    const float* bk    = (const float*)d_in[4];
    const float* wv    = (const float*)d_in[5];
    const float* bv    = (const float*)d_in[6];
    const float* gamma = (const float*)d_in[7];
    float* out = (float*)d_out;

    dim3 g1(NN / 128, RR / 64, MB);
    k_qkv<<<g1, 256>>>(x, wq, bq, wk, bk, wv, bv);

    dim3 g2(NN / 32, MB);
    k_attn<<<g2, 256>>>();

    static int smem_set = 0;
    if (!smem_set) {
        cudaFuncSetAttribute(k_out_wmma,
                             cudaFuncAttributeMaxDynamicSharedMemorySize,
                             SMEM_K3);
        smem_set = 1;
    }
    dim3 g3(NN / 128, CC / 128, MB);
    k_out_wmma<<<g3, 256, SMEM_K3>>>(x, gamma, out);
}

// round 6
// speedup vs baseline: 2.0664x; 1.6687x over previous
#include <cuda_runtime.h>
#include <cstdint>
#include <mma.h>
#include <cuda_bf16.h>

using namespace nvcuda;

// Problem constants (fixed shapes)
#define MB 32      // effective batch m = B*T (raw-reinterpret reshape)
#define CC 256     // channels
#define NN 1024    // pixels per map (32*32)
#define RR 320     // fused qkv rows: 32 q + 32 k + 256 v

typedef unsigned long long u64;

// Scratch (module-load allocated; no cudaMalloc anywhere)
__device__ float g_qkv[MB * RR * NN];                         // 40 MB fp32 q,k,v
__device__ __nv_bfloat16 g_attn_bf[(size_t)MB * NN * NN];     // 67 MB exp(E) bf16
__device__ __nv_bfloat16 g_vb[(size_t)MB * CC * NN];          // 17 MB V*(1/Z) bf16

// ---- packed fp32x2 helpers -------------------------------------------------
__device__ __forceinline__ u64 pack2(float lo, float hi) {
    u64 r; asm("mov.b64 %0,{%1,%2};" : "=l"(r) : "f"(lo), "f"(hi)); return r;
}
__device__ __forceinline__ u64 ffma2(u64 a, u64 b, u64 c) {
    u64 d; asm("fma.rn.f32x2 %0,%1,%2,%3;" : "=l"(d) : "l"(a), "l"(b), "l"(c));
    return d;
}
__device__ __forceinline__ float2 unpack2(u64 v) {
    float2 f; asm("mov.b64 {%0,%1},%2;" : "=f"(f.x), "=f"(f.y) : "l"(v));
    return f;
}

// ---- cp.async helpers (arch-neutral, sm_80+) --------------------------------
__device__ __forceinline__ uint32_t smem_u32(const void* p) {
    uint32_t a;
    asm("{ .reg .u64 t; cvta.to.shared.u64 t, %1; cvt.u32.u64 %0, t; }"
        : "=r"(a) : "l"(p));
    return a;
}
__device__ __forceinline__ void cp16(uint32_t dst, const void* src) {
    asm volatile("cp.async.cg.shared.global [%0], [%1], 16;"
                 :: "r"(dst), "l"(src));
}
#define CP_COMMIT() asm volatile("cp.async.commit_group;" ::: "memory")
#define CP_WAIT(n)  asm volatile("cp.async.wait_group %0;" :: "n"(n) : "memory")

// ---------------------------------------------------------------------------
// Kernel 1: fused QKV projection (FFMA2 path; exact fp32)
// ---------------------------------------------------------------------------
__global__ __launch_bounds__(256) void k_qkv(
    const float* __restrict__ x,
    const float* __restrict__ wq, const float* __restrict__ bq,
    const float* __restrict__ wk, const float* __restrict__ bk,
    const float* __restrict__ wv, const float* __restrict__ bv)
{
    const int m  = blockIdx.z;
    const int r0 = blockIdx.y * 64;
    const int n0 = blockIdx.x * 128;

    __shared__ float AsT[32 * 66];
    __shared__ float Bs[32][128];

    const int tid = threadIdx.x;
    const int tx  = tid & 15;
    const int ty  = tid >> 4;
    const float* xm = x + m * (CC * NN);

    u64 acc2[2][8];
    #pragma unroll
    for (int i = 0; i < 2; i++)
        #pragma unroll
        for (int j = 0; j < 8; j++) acc2[i][j] = 0ull;

    for (int k0 = 0; k0 < CC; k0 += 32) {
        #pragma unroll
        for (int p = 0; p < 8; p++) {
            int l = tid + p * 256;
            int i = l >> 5;
            int k = l & 31;
            int r = r0 + i;
            float w;
            if (r < 32)      w = wq[r * CC + k0 + k];
            else if (r < 64) w = wk[(r - 32) * CC + k0 + k];
            else             w = wv[(r - 64) * CC + k0 + k];
            AsT[k * 66 + i] = w;
        }
        #pragma unroll
        for (int p = 0; p < 4; p++) {
            int f  = tid + p * 256;
            int k  = f >> 5;
            int c4 = f & 31;
            *(float4*)&Bs[k][c4 * 4] =
                *(const float4*)&xm[(k0 + k) * NN + n0 + c4 * 4];
        }
        __syncthreads();

        #pragma unroll
        for (int k = 0; k < 32; k++) {
            const u64* arow = (const u64*)&AsT[k * 66 + ty * 4];
            u64 a0 = arow[0];
            u64 a1 = arow[1];
            float4 b0 = *(const float4*)&Bs[k][tx * 4];
            float4 b1 = *(const float4*)&Bs[k][tx * 4 + 64];
            u64 bd[8];
            bd[0] = pack2(b0.x, b0.x); bd[1] = pack2(b0.y, b0.y);
            bd[2] = pack2(b0.z, b0.z); bd[3] = pack2(b0.w, b0.w);
            bd[4] = pack2(b1.x, b1.x); bd[5] = pack2(b1.y, b1.y);
            bd[6] = pack2(b1.z, b1.z); bd[7] = pack2(b1.w, b1.w);
            #pragma unroll
            for (int j = 0; j < 8; j++) {
                acc2[0][j] = ffma2(a0, bd[j], acc2[0][j]);
                acc2[1][j] = ffma2(a1, bd[j], acc2[1][j]);
            }
        }
        __syncthreads();
    }

    #pragma unroll
    for (int ip = 0; ip < 2; ip++) {
        float2 f[8];
        #pragma unroll
        for (int j = 0; j < 8; j++) f[j] = unpack2(acc2[ip][j]);
        #pragma unroll
        for (int h = 0; h < 2; h++) {
            int r = r0 + ty * 4 + 2 * ip + h;
            float bb = (r < 32) ? bq[r] : ((r < 64) ? bk[r - 32] : bv[r - 64]);
            float* orow = g_qkv + (m * RR + r) * NN + n0;
            float4 v0, v1;
            v0.x = (h ? f[0].y : f[0].x) + bb;
            v0.y = (h ? f[1].y : f[1].x) + bb;
            v0.z = (h ? f[2].y : f[2].x) + bb;
            v0.w = (h ? f[3].y : f[3].x) + bb;
            v1.x = (h ? f[4].y : f[4].x) + bb;
            v1.y = (h ? f[5].y : f[5].x) + bb;
            v1.z = (h ? f[6].y : f[6].x) + bb;
            v1.w = (h ? f[7].y : f[7].x) + bb;
            *(float4*)&orow[tx * 4]      = v0;
            *(float4*)&orow[tx * 4 + 64] = v1;
        }
    }
}

// ---------------------------------------------------------------------------
// Kernel 2: energy + unnormalized softmax (exact fp32 math), bf16 outputs.
// Writes exp(E) bf16 to g_attn_bf; writes V*(1/Z) bf16 to g_vb.
// ---------------------------------------------------------------------------
__global__ __launch_bounds__(256) void k_attn()
{
    const int m  = blockIdx.y;
    const int n0 = blockIdx.x * 32;

    __shared__ float Qs[32][32];
    __shared__ float Ks[32][128];
    __shared__ float izs[32];

    const int tid = threadIdx.x;
    const int r   = tid >> 3;
    const int c8  = tid & 7;

    const float* qbase = g_qkv + m * RR * NN;
    const float* kbase = qbase + 32 * NN;
    __nv_bfloat16* am = g_attn_bf + (size_t)m * NN * NN;

    #pragma unroll
    for (int p = 0; p < 4; p++) {
        int l  = tid + p * 256;
        int o  = l >> 5;
        int rr = l & 31;
        Qs[o][rr] = qbase[o * NN + n0 + rr];
    }

    float ssum = 0.f;
    for (int j0 = 0; j0 < NN; j0 += 128) {
        __syncthreads();
        #pragma unroll
        for (int p = 0; p < 4; p++) {
            int f  = tid + p * 256;
            int o  = f >> 5;
            int c4 = f & 31;
            *(float4*)&Ks[o][c4 * 4] =
                *(const float4*)&kbase[o * NN + j0 + c4 * 4];
        }
        __syncthreads();

        u64 e2[8];
        #pragma unroll
        for (int i = 0; i < 8; i++) e2[i] = 0ull;
        #pragma unroll
        for (int o = 0; o < 32; o++) {
            float qv = Qs[o][r];
            u64 qd = pack2(qv, qv);
            #pragma unroll
            for (int q = 0; q < 4; q++) {
                ulonglong2 kv = *(const ulonglong2*)&Ks[o][c8 * 4 + q * 32];
                e2[q * 2 + 0] = ffma2(qd, kv.x, e2[q * 2 + 0]);
                e2[q * 2 + 1] = ffma2(qd, kv.y, e2[q * 2 + 1]);
            }
        }

        __nv_bfloat16* arow = am + (size_t)(n0 + r) * NN + j0;
        #pragma unroll
        for (int q = 0; q < 4; q++) {
            float2 lo = unpack2(e2[q * 2 + 0]);
            float2 hi = unpack2(e2[q * 2 + 1]);
            float ex0 = __expf(lo.x);
            float ex1 = __expf(lo.y);
            float ex2 = __expf(hi.x);
            float ex3 = __expf(hi.y);
            ssum += (ex0 + ex1) + (ex2 + ex3);
            __nv_bfloat162 h0 = __floats2bfloat162_rn(ex0, ex1);
            __nv_bfloat162 h1 = __floats2bfloat162_rn(ex2, ex3);
            uint2 st;
            st.x = *(uint32_t*)&h0;
            st.y = *(uint32_t*)&h1;
            *(uint2*)&arow[c8 * 4 + q * 32] = st;
        }
    }

    ssum += __shfl_xor_sync(0xffffffffu, ssum, 1);
    ssum += __shfl_xor_sync(0xffffffffu, ssum, 2);
    ssum += __shfl_xor_sync(0xffffffffu, ssum, 4);
    float iz = 1.0f / ssum;
    if (c8 == 0) izs[r] = iz;
    __syncthreads();

    // V'[c][n0+col] = bf16( V[c][n0+col] * iz[n0+col] )
    const float* vm = g_qkv + (m * RR + 64) * NN;
    __nv_bfloat16* vb = g_vb + (size_t)m * CC * NN;
    #pragma unroll
    for (int p = 0; p < 32; p++) {
        int l   = tid + p * 256;
        int c   = l >> 5;
        int col = l & 31;
        float v = vm[c * NN + n0 + col] * izs[col];
        vb[c * NN + n0 + col] = __float2bfloat16(v);
    }
}

// ---------------------------------------------------------------------------
// Kernel 3: out = gamma * (V' @ exp(E)) + x  via bf16 wmma + cp.async pipeline.
// Block tile 128x128, BK=32, 2 stages; 8 warps 2(M)x4(N); warp 64x32 =
// 4x2 frags m16n16k16, 2 k-steps per chunk.
// ---------------------------------------------------------------------------
#define A_LD 40                 // bf16 elements per A row (80B, ldsm conflict-free)
#define B_LD 136                // bf16 elements per B row (272B, ldsm conflict-free)
#define A_BYTES (128 * A_LD * 2)     // 10240
#define B_BYTES (32 * B_LD * 2)      // 8704
#define STAGE_BYTES (A_BYTES + B_BYTES)   // 18944
#define SCR_LD 36
#define SMEM_K3 73728           // max(2*STAGE_BYTES, 8*64*36*4)

__global__ __launch_bounds__(256) void k_out_wmma(
    const float* __restrict__ x, const float* __restrict__ gp,
    float* __restrict__ out)
{
    extern __shared__ __align__(16) char smc[];
    float* smf = (float*)smc;

    const int m  = blockIdx.z;
    const int c0 = blockIdx.y * 128;
    const int j0 = blockIdx.x * 128;

    const int tid = threadIdx.x;
    const int wid = tid >> 5;
    const int lid = tid & 31;
    const int wy  = wid >> 2;        // 0..1  (M dir, 64 rows)
    const int wx  = wid & 3;         // 0..3  (N dir, 32 cols)

    const __nv_bfloat16* vb = g_vb + (size_t)m * CC * NN;
    const __nv_bfloat16* am = g_attn_bf + (size_t)m * NN * NN;
    const uint32_t sbase = smem_u32(smc);

    // per-thread cp.async slots (4 x 16B per chunk)
    const int a_row0 = tid >> 1;             // two A transfers: rows tid/2 (+64)
    const int a_seg0 = (tid & 1) * 2;        // segs {0,1} or {2,3}
    const int b_row  = tid >> 4;             // 0..15 (+16)
    const int b_seg  = tid & 15;

    auto prefetch = [&](int c) {
        const int k0 = c * 32;
        const uint32_t st = sbase + (c & 1) * STAGE_BYTES;
        // A: 128 rows x 64B
        cp16(st + a_row0 * 80 + a_seg0 * 16,
             vb + (size_t)(c0 + a_row0) * NN + k0 + a_seg0 * 8);
        cp16(st + a_row0 * 80 + (a_seg0 + 1) * 16,
             vb + (size_t)(c0 + a_row0) * NN + k0 + (a_seg0 + 1) * 8);
        // B: 32 rows x 256B
        const uint32_t bb = st + A_BYTES;
        cp16(bb + b_row * 272 + b_seg * 16,
             am + (size_t)(k0 + b_row) * NN + j0 + b_seg * 8);
        cp16(bb + (b_row + 16) * 272 + b_seg * 16,
             am + (size_t)(k0 + b_row + 16) * NN + j0 + b_seg * 8);
        CP_COMMIT();
    };

    wmma::fragment<wmma::accumulator, 16, 16, 16, float> acc[4][2];
    #pragma unroll
    for (int i = 0; i < 4; i++)
        #pragma unroll
        for (int j = 0; j < 2; j++) wmma::fill_fragment(acc[i][j], 0.0f);

    prefetch(0);
    for (int c = 0; c < 32; c++) {
        if (c < 31) { prefetch(c + 1); CP_WAIT(1); }
        else        { CP_WAIT(0); }
        __syncthreads();

        const __nv_bfloat16* As =
            (const __nv_bfloat16*)(smc + (c & 1) * STAGE_BYTES);
        const __nv_bfloat16* Bs =
            (const __nv_bfloat16*)(smc + (c & 1) * STAGE_BYTES + A_BYTES);

        #pragma unroll
        for (int kk = 0; kk < 2; kk++) {
            wmma::fragment<wmma::matrix_a, 16, 16, 16, __nv_bfloat16,
                           wmma::row_major> af[4];
            wmma::fragment<wmma::matrix_b, 16, 16, 16, __nv_bfloat16,
                           wmma::row_major> bf[2];
            #pragma unroll
            for (int i = 0; i < 4; i++)
                wmma::load_matrix_sync(af[i],
                    &As[(wy * 64 + i * 16) * A_LD + kk * 16], A_LD);
            #pragma unroll
            for (int j = 0; j < 2; j++)
                wmma::load_matrix_sync(bf[j],
                    &Bs[kk * 16 * B_LD + wx * 32 + j * 16], B_LD);
            #pragma unroll
            for (int i = 0; i < 4; i++)
                #pragma unroll
                for (int j = 0; j < 2; j++)
                    wmma::mma_sync(acc[i][j], af[i], bf[j], acc[i][j]);
        }
        __syncthreads();
    }

    // ---- epilogue: frags -> smem scratch (fp32) -> gamma*acc + x -> gmem ----
    float* ws = smf + wid * (64 * SCR_LD);
    #pragma unroll
    for (int i = 0; i < 4; i++)
        #pragma unroll
        for (int j = 0; j < 2; j++)
            wmma::store_matrix_sync(&ws[(i * 16) * SCR_LD + j * 16],
                                    acc[i][j], SCR_LD, wmma::mem_row_major);
    __syncwarp();

    const float g = *gp;
    const int rbase = c0 + wy * 64;
    const int cbase = j0 + wx * 32;
    const float* xm = x + (size_t)m * CC * NN;
    float* om = out + (size_t)m * CC * NN;
    #pragma unroll
    for (int it = 0; it < 16; it++) {
        int r  = it * 4 + (lid >> 3);
        int c4 = lid & 7;
        float4 a  = *(const float4*)&ws[r * SCR_LD + c4 * 4];
        const float* xrow = xm + (size_t)(rbase + r) * NN + cbase;
        float4 xv = *(const float4*)&xrow[c4 * 4];
        float4 o;
        o.x = g * a.x + xv.x;
        o.y = g * a.y + xv.y;
        o.z = g * a.z + xv.z;
        o.w = g * a.w + xv.w;
        *(float4*)&om[(size_t)(rbase + r) * NN + cbase + c4 * 4] = o;
    }
}

// ---------------------------------------------------------------------------
extern "C" void kernel_launch(void* const* d_in, const int* in_sizes, int n_in,
                              void* d_out, int out_size)
{
    const float* x     = (const float*)d_in[0];
    const float* wq    = (const float*)d_in[1];
    const float* bq    = (const float*)d_in[2];
    const float* wk    = (const float*)d_in[3];
    const float* bk    = (const float*)d_in[4];
    const float* wv    = (const float*)d_in[5];
    const float* bv    = (const float*)d_in[6];
    const float* gamma = (const float*)d_in[7];
    float* out = (float*)d_out;

    cudaFuncSetAttribute(k_out_wmma,
                         cudaFuncAttributeMaxDynamicSharedMemorySize, SMEM_K3);

    dim3 g1(NN / 128, RR / 64, MB);
    k_qkv<<<g1, 256>>>(x, wq, bq, wk, bk, wv, bv);

    dim3 g2(NN / 32, MB);
    k_attn<<<g2, 256>>>();

    dim3 g3(NN / 128, CC / 128, MB);
    k_out_wmma<<<g3, 256, SMEM_K3>>>(x, gamma, out);
}

// round 7
// speedup vs baseline: 2.4534x; 1.1873x over previous
#include <cuda_runtime.h>
#include <cstdint>
#include <mma.h>
#include <cuda_bf16.h>

using namespace nvcuda;

// Problem constants (fixed shapes)
#define MB 32      // effective batch m = B*T (raw-reinterpret reshape)
#define CC 256     // channels
#define NN 1024    // pixels per map (32*32)
#define RR 320     // fused qkv rows: 32 q + 32 k + 256 v

typedef unsigned long long u64;

// Scratch (module-load allocated; no cudaMalloc anywhere)
__device__ float g_qkv[MB * RR * NN];                         // 40 MB fp32 q,k,v
__device__ __nv_bfloat16 g_attn_bf[(size_t)MB * NN * NN];     // 67 MB exp(E) bf16
__device__ __nv_bfloat16 g_vb[(size_t)MB * CC * NN];          // 17 MB V*(1/Z) bf16

// ---- packed fp32x2 helpers -------------------------------------------------
__device__ __forceinline__ u64 pack2(float lo, float hi) {
    u64 r; asm("mov.b64 %0,{%1,%2};" : "=l"(r) : "f"(lo), "f"(hi)); return r;
}
__device__ __forceinline__ u64 ffma2(u64 a, u64 b, u64 c) {
    u64 d; asm("fma.rn.f32x2 %0,%1,%2,%3;" : "=l"(d) : "l"(a), "l"(b), "l"(c));
    return d;
}
__device__ __forceinline__ float2 unpack2(u64 v) {
    float2 f; asm("mov.b64 {%0,%1},%2;" : "=f"(f.x), "=f"(f.y) : "l"(v));
    return f;
}

// ---- cp.async helpers (arch-neutral, sm_80+) --------------------------------
__device__ __forceinline__ uint32_t smem_u32(const void* p) {
    uint32_t a;
    asm("{ .reg .u64 t; cvta.to.shared.u64 t, %1; cvt.u32.u64 %0, t; }"
        : "=r"(a) : "l"(p));
    return a;
}
__device__ __forceinline__ void cp16(uint32_t dst, const void* src) {
    asm volatile("cp.async.cg.shared.global [%0], [%1], 16;"
                 :: "r"(dst), "l"(src));
}
#define CP_COMMIT() asm volatile("cp.async.commit_group;" ::: "memory")
#define CP_WAIT(n)  asm volatile("cp.async.wait_group %0;" :: "n"(n) : "memory")

// ---------------------------------------------------------------------------
// Kernel 1: fused QKV projection via tf32 wmma + cp.async 2-stage pipeline.
// P[320][1024] = W'(320x256) @ X(256x1024) + b'. Block tile 64x128, BK=32,
// 8 warps as 2(M)x4(N), warp tile 32x32 = 2x2 frags m16n16k8.
// fp32 inputs consumed as tf32 (HW truncation); fp32 accumulate; fp32 out.
// ---------------------------------------------------------------------------
#define K1_A_LD 40                      // fp32 elems per A row (160B)
#define K1_B_LD 136                     // fp32 elems per B row (544B)
#define K1_A_BYTES (64 * K1_A_LD * 4)   // 10240
#define K1_B_BYTES (32 * K1_B_LD * 4)   // 17408
#define K1_STAGE (K1_A_BYTES + K1_B_BYTES)  // 27648
#define K1_SCR_LD 36
#define SMEM_K1 (2 * K1_STAGE)          // 55296 >= scratch 36864

__global__ __launch_bounds__(256) void k_qkv_wmma(
    const float* __restrict__ x,
    const float* __restrict__ wq, const float* __restrict__ bq,
    const float* __restrict__ wk, const float* __restrict__ bk,
    const float* __restrict__ wv, const float* __restrict__ bv)
{
    extern __shared__ __align__(16) char smc[];
    float* smf = (float*)smc;

    const int m  = blockIdx.z;
    const int r0 = blockIdx.y * 64;
    const int n0 = blockIdx.x * 128;

    const int tid = threadIdx.x;
    const int wid = tid >> 5;
    const int lid = tid & 31;
    const int wy  = wid >> 2;        // 0..1 (32 rows)
    const int wx  = wid & 3;         // 0..3 (32 cols)

    const float* xm = x + (size_t)m * CC * NN;
    const uint32_t sbase = smem_u32(smc);

    // per-thread cp.async assignments
    const int ar = tid >> 2;         // A row 0..63
    const int as = tid & 3;          // A seg pair {as, as+4}
    const int gr_a = r0 + ar;
    const float* wrow = (gr_a < 32) ? wq + gr_a * CC
                      : (gr_a < 64) ? wk + (gr_a - 32) * CC
                                    : wv + (gr_a - 64) * CC;
    const int br = tid >> 3;         // B row 0..31
    const int bs = tid & 7;          // B seg 0..7 (+8,16,24)

    auto prefetch = [&](int c) {
        const int k0 = c * 32;
        const uint32_t st = sbase + (c & 1) * K1_STAGE;
        cp16(st + ar * 160 + as * 16, wrow + k0 + as * 4);
        cp16(st + ar * 160 + (as + 4) * 16, wrow + k0 + (as + 4) * 4);
        const uint32_t bb = st + K1_A_BYTES;
        #pragma unroll
        for (int j = 0; j < 4; j++)
            cp16(bb + br * 544 + (bs + j * 8) * 16,
                 xm + (size_t)(k0 + br) * NN + n0 + (bs + j * 8) * 4);
        CP_COMMIT();
    };

    wmma::fragment<wmma::accumulator, 16, 16, 8, float> acc[2][2];
    #pragma unroll
    for (int i = 0; i < 2; i++)
        #pragma unroll
        for (int j = 0; j < 2; j++) wmma::fill_fragment(acc[i][j], 0.0f);

    prefetch(0);
    for (int c = 0; c < 8; c++) {
        if (c < 7) { prefetch(c + 1); CP_WAIT(1); }
        else       { CP_WAIT(0); }
        __syncthreads();

        const float* As = (const float*)(smc + (c & 1) * K1_STAGE);
        const float* Bs = (const float*)(smc + (c & 1) * K1_STAGE + K1_A_BYTES);

        #pragma unroll
        for (int kk = 0; kk < 4; kk++) {
            wmma::fragment<wmma::matrix_a, 16, 16, 8, wmma::precision::tf32,
                           wmma::row_major> af[2];
            wmma::fragment<wmma::matrix_b, 16, 16, 8, wmma::precision::tf32,
                           wmma::row_major> bf[2];
            #pragma unroll
            for (int i = 0; i < 2; i++)
                wmma::load_matrix_sync(af[i],
                    &As[(wy * 32 + i * 16) * K1_A_LD + kk * 8], K1_A_LD);
            #pragma unroll
            for (int j = 0; j < 2; j++)
                wmma::load_matrix_sync(bf[j],
                    &Bs[kk * 8 * K1_B_LD + wx * 32 + j * 16], K1_B_LD);
            #pragma unroll
            for (int i = 0; i < 2; i++)
                #pragma unroll
                for (int j = 0; j < 2; j++)
                    wmma::mma_sync(acc[i][j], af[i], bf[j], acc[i][j]);
        }
        __syncthreads();
    }

    // epilogue: frags -> smem scratch -> +bias -> g_qkv (fp32)
    float* ws = smf + wid * (32 * K1_SCR_LD);
    #pragma unroll
    for (int i = 0; i < 2; i++)
        #pragma unroll
        for (int j = 0; j < 2; j++)
            wmma::store_matrix_sync(&ws[(i * 16) * K1_SCR_LD + j * 16],
                                    acc[i][j], K1_SCR_LD, wmma::mem_row_major);
    __syncwarp();

    #pragma unroll
    for (int it = 0; it < 8; it++) {
        int r  = it * 4 + (lid >> 3);
        int c4 = lid & 7;
        int gr = r0 + wy * 32 + r;
        float bb = (gr < 32) ? bq[gr] : ((gr < 64) ? bk[gr - 32] : bv[gr - 64]);
        float4 a = *(const float4*)&ws[r * K1_SCR_LD + c4 * 4];
        a.x += bb; a.y += bb; a.z += bb; a.w += bb;
        *(float4*)&g_qkv[(size_t)(m * RR + gr) * NN + n0 + wx * 32 + c4 * 4] = a;
    }
}

// ---------------------------------------------------------------------------
// Kernel 2: energy + unnormalized softmax (exact fp32 math), bf16 outputs.
// Writes exp(E) bf16 to g_attn_bf; writes V*(1/Z) bf16 to g_vb.
// ---------------------------------------------------------------------------
__global__ __launch_bounds__(256) void k_attn()
{
    const int m  = blockIdx.y;
    const int n0 = blockIdx.x * 32;

    __shared__ float Qs[32][32];
    __shared__ float Ks[32][128];
    __shared__ float izs[32];

    const int tid = threadIdx.x;
    const int r   = tid >> 3;
    const int c8  = tid & 7;

    const float* qbase = g_qkv + m * RR * NN;
    const float* kbase = qbase + 32 * NN;
    __nv_bfloat16* am = g_attn_bf + (size_t)m * NN * NN;

    #pragma unroll
    for (int p = 0; p < 4; p++) {
        int l  = tid + p * 256;
        int o  = l >> 5;
        int rr = l & 31;
        Qs[o][rr] = qbase[o * NN + n0 + rr];
    }

    float ssum = 0.f;
    for (int j0 = 0; j0 < NN; j0 += 128) {
        __syncthreads();
        #pragma unroll
        for (int p = 0; p < 4; p++) {
            int f  = tid + p * 256;
            int o  = f >> 5;
            int c4 = f & 31;
            *(float4*)&Ks[o][c4 * 4] =
                *(const float4*)&kbase[o * NN + j0 + c4 * 4];
        }
        __syncthreads();

        u64 e2[8];
        #pragma unroll
        for (int i = 0; i < 8; i++) e2[i] = 0ull;
        #pragma unroll
        for (int o = 0; o < 32; o++) {
            float qv = Qs[o][r];
            u64 qd = pack2(qv, qv);
            #pragma unroll
            for (int q = 0; q < 4; q++) {
                ulonglong2 kv = *(const ulonglong2*)&Ks[o][c8 * 4 + q * 32];
                e2[q * 2 + 0] = ffma2(qd, kv.x, e2[q * 2 + 0]);
                e2[q * 2 + 1] = ffma2(qd, kv.y, e2[q * 2 + 1]);
            }
        }

        __nv_bfloat16* arow = am + (size_t)(n0 + r) * NN + j0;
        #pragma unroll
        for (int q = 0; q < 4; q++) {
            float2 lo = unpack2(e2[q * 2 + 0]);
            float2 hi = unpack2(e2[q * 2 + 1]);
            float ex0 = __expf(lo.x);
            float ex1 = __expf(lo.y);
            float ex2 = __expf(hi.x);
            float ex3 = __expf(hi.y);
            ssum += (ex0 + ex1) + (ex2 + ex3);
            __nv_bfloat162 h0 = __floats2bfloat162_rn(ex0, ex1);
            __nv_bfloat162 h1 = __floats2bfloat162_rn(ex2, ex3);
            uint2 st;
            st.x = *(uint32_t*)&h0;
            st.y = *(uint32_t*)&h1;
            *(uint2*)&arow[c8 * 4 + q * 32] = st;
        }
    }

    ssum += __shfl_xor_sync(0xffffffffu, ssum, 1);
    ssum += __shfl_xor_sync(0xffffffffu, ssum, 2);
    ssum += __shfl_xor_sync(0xffffffffu, ssum, 4);
    float iz = 1.0f / ssum;
    if (c8 == 0) izs[r] = iz;
    __syncthreads();

    // V'[c][n0+col] = bf16( V[c][n0+col] * iz[n0+col] )
    const float* vm = g_qkv + (m * RR + 64) * NN;
    __nv_bfloat16* vb = g_vb + (size_t)m * CC * NN;
    #pragma unroll
    for (int p = 0; p < 32; p++) {
        int l   = tid + p * 256;
        int c   = l >> 5;
        int col = l & 31;
        float v = vm[c * NN + n0 + col] * izs[col];
        vb[c * NN + n0 + col] = __float2bfloat16(v);
    }
}

// ---------------------------------------------------------------------------
// Kernel 3: out = gamma * (V' @ exp(E)) + x  via bf16 wmma + cp.async pipeline.
// ---------------------------------------------------------------------------
#define A_LD 40
#define B_LD 136
#define A_BYTES (128 * A_LD * 2)
#define B_BYTES (32 * B_LD * 2)
#define STAGE_BYTES (A_BYTES + B_BYTES)
#define SCR_LD 36
#define SMEM_K3 73728

__global__ __launch_bounds__(256) void k_out_wmma(
    const float* __restrict__ x, const float* __restrict__ gp,
    float* __restrict__ out)
{
    extern __shared__ __align__(16) char smc[];
    float* smf = (float*)smc;

    const int m  = blockIdx.z;
    const int c0 = blockIdx.y * 128;
    const int j0 = blockIdx.x * 128;

    const int tid = threadIdx.x;
    const int wid = tid >> 5;
    const int lid = tid & 31;
    const int wy  = wid >> 2;
    const int wx  = wid & 3;

    const __nv_bfloat16* vb = g_vb + (size_t)m * CC * NN;
    const __nv_bfloat16* am = g_attn_bf + (size_t)m * NN * NN;
    const uint32_t sbase = smem_u32(smc);

    const int a_row0 = tid >> 1;
    const int a_seg0 = (tid & 1) * 2;
    const int b_row  = tid >> 4;
    const int b_seg  = tid & 15;

    auto prefetch = [&](int c) {
        const int k0 = c * 32;
        const uint32_t st = sbase + (c & 1) * STAGE_BYTES;
        cp16(st + a_row0 * 80 + a_seg0 * 16,
             vb + (size_t)(c0 + a_row0) * NN + k0 + a_seg0 * 8);
        cp16(st + a_row0 * 80 + (a_seg0 + 1) * 16,
             vb + (size_t)(c0 + a_row0) * NN + k0 + (a_seg0 + 1) * 8);
        const uint32_t bb = st + A_BYTES;
        cp16(bb + b_row * 272 + b_seg * 16,
             am + (size_t)(k0 + b_row) * NN + j0 + b_seg * 8);
        cp16(bb + (b_row + 16) * 272 + b_seg * 16,
             am + (size_t)(k0 + b_row + 16) * NN + j0 + b_seg * 8);
        CP_COMMIT();
    };

    wmma::fragment<wmma::accumulator, 16, 16, 16, float> acc[4][2];
    #pragma unroll
    for (int i = 0; i < 4; i++)
        #pragma unroll
        for (int j = 0; j < 2; j++) wmma::fill_fragment(acc[i][j], 0.0f);

    prefetch(0);
    for (int c = 0; c < 32; c++) {
        if (c < 31) { prefetch(c + 1); CP_WAIT(1); }
        else        { CP_WAIT(0); }
        __syncthreads();

        const __nv_bfloat16* As =
            (const __nv_bfloat16*)(smc + (c & 1) * STAGE_BYTES);
        const __nv_bfloat16* Bs =
            (const __nv_bfloat16*)(smc + (c & 1) * STAGE_BYTES + A_BYTES);

        #pragma unroll
        for (int kk = 0; kk < 2; kk++) {
            wmma::fragment<wmma::matrix_a, 16, 16, 16, __nv_bfloat16,
                           wmma::row_major> af[4];
            wmma::fragment<wmma::matrix_b, 16, 16, 16, __nv_bfloat16,
                           wmma::row_major> bf[2];
            #pragma unroll
            for (int i = 0; i < 4; i++)
                wmma::load_matrix_sync(af[i],
                    &As[(wy * 64 + i * 16) * A_LD + kk * 16], A_LD);
            #pragma unroll
            for (int j = 0; j < 2; j++)
                wmma::load_matrix_sync(bf[j],
                    &Bs[kk * 16 * B_LD + wx * 32 + j * 16], B_LD);
            #pragma unroll
            for (int i = 0; i < 4; i++)
                #pragma unroll
                for (int j = 0; j < 2; j++)
                    wmma::mma_sync(acc[i][j], af[i], bf[j], acc[i][j]);
        }
        __syncthreads();
    }

    float* ws = smf + wid * (64 * SCR_LD);
    #pragma unroll
    for (int i = 0; i < 4; i++)
        #pragma unroll
        for (int j = 0; j < 2; j++)
            wmma::store_matrix_sync(&ws[(i * 16) * SCR_LD + j * 16],
                                    acc[i][j], SCR_LD, wmma::mem_row_major);
    __syncwarp();

    const float g = *gp;
    const int rbase = c0 + wy * 64;
    const int cbase = j0 + wx * 32;
    const float* xm = x + (size_t)m * CC * NN;
    float* om = out + (size_t)m * CC * NN;
    #pragma unroll
    for (int it = 0; it < 16; it++) {
        int r  = it * 4 + (lid >> 3);
        int c4 = lid & 7;
        float4 a  = *(const float4*)&ws[r * SCR_LD + c4 * 4];
        const float* xrow = xm + (size_t)(rbase + r) * NN + cbase;
        float4 xv = *(const float4*)&xrow[c4 * 4];
        float4 o;
        o.x = g * a.x + xv.x;
        o.y = g * a.y + xv.y;
        o.z = g * a.z + xv.z;
        o.w = g * a.w + xv.w;
        *(float4*)&om[(size_t)(rbase + r) * NN + cbase + c4 * 4] = o;
    }
}

// ---------------------------------------------------------------------------
extern "C" void kernel_launch(void* const* d_in, const int* in_sizes, int n_in,
                              void* d_out, int out_size)
{
    const float* x     = (const float*)d_in[0];
    const float* wq    = (const float*)d_in[1];
    const float* bq    = (const float*)d_in[2];
    const float* wk    = (const float*)d_in[3];
    const float* bk    = (const float*)d_in[4];
    const float* wv    = (const float*)d_in[5];
    const float* bv    = (const float*)d_in[6];
    const float* gamma = (const float*)d_in[7];
    float* out = (float*)d_out;

    cudaFuncSetAttribute(k_qkv_wmma,
                         cudaFuncAttributeMaxDynamicSharedMemorySize, SMEM_K1);
    cudaFuncSetAttribute(k_out_wmma,
                         cudaFuncAttributeMaxDynamicSharedMemorySize, SMEM_K3);

    dim3 g1(NN / 128, RR / 64, MB);
    k_qkv_wmma<<<g1, 256, SMEM_K1>>>(x, wq, bq, wk, bk, wv, bv);

    dim3 g2(NN / 32, MB);
    k_attn<<<g2, 256>>>();

    dim3 g3(NN / 128, CC / 128, MB);
    k_out_wmma<<<g3, 256, SMEM_K3>>>(x, gamma, out);
}

// round 8
// speedup vs baseline: 2.9975x; 1.2218x over previous
#include <cuda_runtime.h>
#include <cstdint>
#include <mma.h>
#include <cuda_bf16.h>

using namespace nvcuda;

// Problem constants (fixed shapes)
#define MB 32      // effective batch m = B*T (raw-reinterpret reshape)
#define CC 256     // channels
#define NN 1024    // pixels per map (32*32)
#define RR 320     // fused qkv rows: 32 q + 32 k + 256 v

typedef unsigned long long u64;

// Scratch (module-load allocated; no cudaMalloc anywhere)
__device__ float g_qkv[MB * RR * NN];                         // 40 MB fp32 q,k,v
__device__ __nv_bfloat16 g_attn_bf[(size_t)MB * NN * NN];     // 67 MB exp(E) bf16
__device__ __nv_bfloat16 g_vb[(size_t)MB * CC * NN];          // 17 MB V*(1/Z) bf16

// ---- cp.async helpers (arch-neutral, sm_80+) --------------------------------
__device__ __forceinline__ uint32_t smem_u32(const void* p) {
    uint32_t a;
    asm("{ .reg .u64 t; cvta.to.shared.u64 t, %1; cvt.u32.u64 %0, t; }"
        : "=r"(a) : "l"(p));
    return a;
}
__device__ __forceinline__ void cp16(uint32_t dst, const void* src) {
    asm volatile("cp.async.cg.shared.global [%0], [%1], 16;"
                 :: "r"(dst), "l"(src));
}
#define CP_COMMIT() asm volatile("cp.async.commit_group;" ::: "memory")
#define CP_WAIT(n)  asm volatile("cp.async.wait_group %0;" :: "n"(n) : "memory")

// ---------------------------------------------------------------------------
// Kernel 1: fused QKV projection via tf32 wmma + cp.async 2-stage pipeline.
// ---------------------------------------------------------------------------
#define K1_A_LD 40
#define K1_B_LD 136
#define K1_A_BYTES (64 * K1_A_LD * 4)
#define K1_B_BYTES (32 * K1_B_LD * 4)
#define K1_STAGE (K1_A_BYTES + K1_B_BYTES)
#define K1_SCR_LD 36
#define SMEM_K1 (2 * K1_STAGE)

__global__ __launch_bounds__(256) void k_qkv_wmma(
    const float* __restrict__ x,
    const float* __restrict__ wq, const float* __restrict__ bq,
    const float* __restrict__ wk, const float* __restrict__ bk,
    const float* __restrict__ wv, const float* __restrict__ bv)
{
    extern __shared__ __align__(16) char smc[];
    float* smf = (float*)smc;

    const int m  = blockIdx.z;
    const int r0 = blockIdx.y * 64;
    const int n0 = blockIdx.x * 128;

    const int tid = threadIdx.x;
    const int wid = tid >> 5;
    const int lid = tid & 31;
    const int wy  = wid >> 2;
    const int wx  = wid & 3;

    const float* xm = x + (size_t)m * CC * NN;
    const uint32_t sbase = smem_u32(smc);

    const int ar = tid >> 2;
    const int as = tid & 3;
    const int gr_a = r0 + ar;
    const float* wrow = (gr_a < 32) ? wq + gr_a * CC
                      : (gr_a < 64) ? wk + (gr_a - 32) * CC
                                    : wv + (gr_a - 64) * CC;
    const int br = tid >> 3;
    const int bs = tid & 7;

    auto prefetch = [&](int c) {
        const int k0 = c * 32;
        const uint32_t st = sbase + (c & 1) * K1_STAGE;
        cp16(st + ar * 160 + as * 16, wrow + k0 + as * 4);
        cp16(st + ar * 160 + (as + 4) * 16, wrow + k0 + (as + 4) * 4);
        const uint32_t bb = st + K1_A_BYTES;
        #pragma unroll
        for (int j = 0; j < 4; j++)
            cp16(bb + br * 544 + (bs + j * 8) * 16,
                 xm + (size_t)(k0 + br) * NN + n0 + (bs + j * 8) * 4);
        CP_COMMIT();
    };

    wmma::fragment<wmma::accumulator, 16, 16, 8, float> acc[2][2];
    #pragma unroll
    for (int i = 0; i < 2; i++)
        #pragma unroll
        for (int j = 0; j < 2; j++) wmma::fill_fragment(acc[i][j], 0.0f);

    prefetch(0);
    for (int c = 0; c < 8; c++) {
        if (c < 7) { prefetch(c + 1); CP_WAIT(1); }
        else       { CP_WAIT(0); }
        __syncthreads();

        const float* As = (const float*)(smc + (c & 1) * K1_STAGE);
        const float* Bs = (const float*)(smc + (c & 1) * K1_STAGE + K1_A_BYTES);

        #pragma unroll
        for (int kk = 0; kk < 4; kk++) {
            wmma::fragment<wmma::matrix_a, 16, 16, 8, wmma::precision::tf32,
                           wmma::row_major> af[2];
            wmma::fragment<wmma::matrix_b, 16, 16, 8, wmma::precision::tf32,
                           wmma::row_major> bf[2];
            #pragma unroll
            for (int i = 0; i < 2; i++)
                wmma::load_matrix_sync(af[i],
                    &As[(wy * 32 + i * 16) * K1_A_LD + kk * 8], K1_A_LD);
            #pragma unroll
            for (int j = 0; j < 2; j++)
                wmma::load_matrix_sync(bf[j],
                    &Bs[kk * 8 * K1_B_LD + wx * 32 + j * 16], K1_B_LD);
            #pragma unroll
            for (int i = 0; i < 2; i++)
                #pragma unroll
                for (int j = 0; j < 2; j++)
                    wmma::mma_sync(acc[i][j], af[i], bf[j], acc[i][j]);
        }
        __syncthreads();
    }

    float* ws = smf + wid * (32 * K1_SCR_LD);
    #pragma unroll
    for (int i = 0; i < 2; i++)
        #pragma unroll
        for (int j = 0; j < 2; j++)
            wmma::store_matrix_sync(&ws[(i * 16) * K1_SCR_LD + j * 16],
                                    acc[i][j], K1_SCR_LD, wmma::mem_row_major);
    __syncwarp();

    #pragma unroll
    for (int it = 0; it < 8; it++) {
        int r  = it * 4 + (lid >> 3);
        int c4 = lid & 7;
        int gr = r0 + wy * 32 + r;
        float bb = (gr < 32) ? bq[gr] : ((gr < 64) ? bk[gr - 32] : bv[gr - 64]);
        float4 a = *(const float4*)&ws[r * K1_SCR_LD + c4 * 4];
        a.x += bb; a.y += bb; a.z += bb; a.w += bb;
        *(float4*)&g_qkv[(size_t)(m * RR + gr) * NN + n0 + wx * 32 + c4 * 4] = a;
    }
}

// ---------------------------------------------------------------------------
// Kernel 2: energy + exp + rowsum via tf32 wmma, fused bf16 emit.
// Block = 128 energy rows x full 1024 cols of one batch, 8 column slabs.
// A = Q (col-major natural: Qs[o][n]); B = K (row-major natural: Ks[o][j]).
// exp(E) -> g_attn_bf; V*(1/Z) -> g_vb.
// ---------------------------------------------------------------------------
#define K2_Q_LD 132
#define K2_K_LD 136
#define K2_S_LD 132
#define K2_Q   0                       // 32 x 132 fp32
#define K2_K   (32 * K2_Q_LD)          // 2 x (32 x 136) fp32
#define K2_SCR (K2_K + 2 * 32 * K2_K_LD)
#define K2_SUM (K2_SCR + 128 * K2_S_LD)
#define SMEM_K2 ((K2_SUM + 128) * 4)   // 119808 B

__global__ __launch_bounds__(256) void k_attn_wmma()
{
    extern __shared__ __align__(16) char smc[];
    float* smf = (float*)smc;
    float* Qs  = smf + K2_Q;
    float* scr = smf + K2_SCR;
    float* rsum = smf + K2_SUM;

    const int m  = blockIdx.y;
    const int n0 = blockIdx.x * 128;

    const int tid = threadIdx.x;
    const int wid = tid >> 5;
    const int lid = tid & 31;
    const int wy  = wid >> 2;        // 0..1 (64 rows)
    const int wx  = wid & 3;         // 0..3 (32 cols)

    const float* qbase = g_qkv + (size_t)m * RR * NN;
    const float* kbase = qbase + 32 * NN;
    __nv_bfloat16* am = g_attn_bf + (size_t)m * NN * NN;

    const uint32_t sbase = smem_u32(smc);
    const uint32_t qb = sbase + K2_Q * 4;
    const uint32_t kb = sbase + K2_K * 4;

    if (tid < 128) rsum[tid] = 0.f;

    // Q tile: Qs[o][r] = q[o][n0+r]; rows 528B (33x16B)
    #pragma unroll
    for (int p = 0; p < 4; p++) {
        int idx = tid + p * 256;
        int o   = idx >> 5;
        int sg  = idx & 31;
        cp16(qb + o * 528 + sg * 16, qbase + (size_t)o * NN + n0 + sg * 4);
    }
    // K slab prefetch: Ks[o][j], rows 544B (34x16B)
    auto prefetch = [&](int s) {
        const uint32_t st = kb + (s & 1) * (32 * K2_K_LD * 4);
        const int j0 = s * 128;
        #pragma unroll
        for (int p = 0; p < 4; p++) {
            int idx = tid + p * 256;
            int o   = idx >> 5;
            int sg  = idx & 31;
            cp16(st + o * 544 + sg * 16, kbase + (size_t)o * NN + j0 + sg * 4);
        }
        CP_COMMIT();
    };
    prefetch(0);   // group 0 includes Q + K0

    for (int s = 0; s < 8; s++) {
        if (s < 7) { prefetch(s + 1); CP_WAIT(1); }
        else       { CP_WAIT(0); }
        __syncthreads();

        const float* Ks = smf + K2_K + (s & 1) * (32 * K2_K_LD);

        wmma::fragment<wmma::accumulator, 16, 16, 8, float> acc[4][2];
        #pragma unroll
        for (int i = 0; i < 4; i++)
            #pragma unroll
            for (int j = 0; j < 2; j++) wmma::fill_fragment(acc[i][j], 0.0f);

        #pragma unroll
        for (int kk = 0; kk < 4; kk++) {
            wmma::fragment<wmma::matrix_a, 16, 16, 8, wmma::precision::tf32,
                           wmma::col_major> af[4];
            wmma::fragment<wmma::matrix_b, 16, 16, 8, wmma::precision::tf32,
                           wmma::row_major> bf[2];
            #pragma unroll
            for (int i = 0; i < 4; i++)
                wmma::load_matrix_sync(af[i],
                    &Qs[(kk * 8) * K2_Q_LD + wy * 64 + i * 16], K2_Q_LD);
            #pragma unroll
            for (int j = 0; j < 2; j++)
                wmma::load_matrix_sync(bf[j],
                    &Ks[(kk * 8) * K2_K_LD + wx * 32 + j * 16], K2_K_LD);
            #pragma unroll
            for (int i = 0; i < 4; i++)
                #pragma unroll
                for (int j = 0; j < 2; j++)
                    wmma::mma_sync(acc[i][j], af[i], bf[j], acc[i][j]);
        }

        #pragma unroll
        for (int i = 0; i < 4; i++)
            #pragma unroll
            for (int j = 0; j < 2; j++)
                wmma::store_matrix_sync(
                    &scr[(wy * 64 + i * 16) * K2_S_LD + wx * 32 + j * 16],
                    acc[i][j], K2_S_LD, wmma::mem_row_major);
        __syncthreads();

        // exp + rowsum + bf16 store: thread -> row tid>>1, half tid&1 (64 cols)
        {
            const int r    = tid >> 1;
            const int half = tid & 1;
            const float* srow = &scr[r * K2_S_LD + half * 64];
            __nv_bfloat16* arow = am + (size_t)(n0 + r) * NN + s * 128 + half * 64;
            float ssum = 0.f;
            #pragma unroll
            for (int it = 0; it < 8; it++) {
                float4 e0 = *(const float4*)&srow[it * 8];
                float4 e1 = *(const float4*)&srow[it * 8 + 4];
                float x0 = __expf(e0.x), x1 = __expf(e0.y);
                float x2 = __expf(e0.z), x3 = __expf(e0.w);
                float x4 = __expf(e1.x), x5 = __expf(e1.y);
                float x6 = __expf(e1.z), x7 = __expf(e1.w);
                ssum += ((x0 + x1) + (x2 + x3)) + ((x4 + x5) + (x6 + x7));
                __nv_bfloat162 h0 = __floats2bfloat162_rn(x0, x1);
                __nv_bfloat162 h1 = __floats2bfloat162_rn(x2, x3);
                __nv_bfloat162 h2 = __floats2bfloat162_rn(x4, x5);
                __nv_bfloat162 h3 = __floats2bfloat162_rn(x6, x7);
                uint4 st;
                st.x = *(uint32_t*)&h0; st.y = *(uint32_t*)&h1;
                st.z = *(uint32_t*)&h2; st.w = *(uint32_t*)&h3;
                *(uint4*)&arow[it * 8] = st;
            }
            ssum += __shfl_xor_sync(0xffffffffu, ssum, 1);
            if (half == 0) rsum[r] += ssum;
        }
        __syncthreads();
    }

    // invert row sums
    if (tid < 128) rsum[tid] = 1.0f / rsum[tid];
    __syncthreads();

    // V'[c][n0+col] = bf16( V[c][n0+col] * iz[col] ), 256 rows x 128 cols
    const float* vm = g_qkv + (size_t)(m * RR + 64) * NN;
    __nv_bfloat16* vb = g_vb + (size_t)m * CC * NN;
    const int col4 = (tid & 31) * 4;
    const float4 izv = *(const float4*)&rsum[col4];
    #pragma unroll
    for (int p = 0; p < 32; p++) {
        int c = p * 8 + (tid >> 5);
        float4 v = *(const float4*)&vm[(size_t)c * NN + n0 + col4];
        v.x *= izv.x; v.y *= izv.y; v.z *= izv.z; v.w *= izv.w;
        __nv_bfloat162 h0 = __floats2bfloat162_rn(v.x, v.y);
        __nv_bfloat162 h1 = __floats2bfloat162_rn(v.z, v.w);
        uint2 st;
        st.x = *(uint32_t*)&h0; st.y = *(uint32_t*)&h1;
        *(uint2*)&vb[(size_t)c * NN + n0 + col4] = st;
    }
}

// ---------------------------------------------------------------------------
// Kernel 3: out = gamma * (V' @ exp(E)) + x  via bf16 wmma + cp.async pipeline.
// ---------------------------------------------------------------------------
#define A_LD 40
#define B_LD 136
#define A_BYTES (128 * A_LD * 2)
#define B_BYTES (32 * B_LD * 2)
#define STAGE_BYTES (A_BYTES + B_BYTES)
#define SCR_LD 36
#define SMEM_K3 73728

__global__ __launch_bounds__(256) void k_out_wmma(
    const float* __restrict__ x, const float* __restrict__ gp,
    float* __restrict__ out)
{
    extern __shared__ __align__(16) char smc[];
    float* smf = (float*)smc;

    const int m  = blockIdx.z;
    const int c0 = blockIdx.y * 128;
    const int j0 = blockIdx.x * 128;

    const int tid = threadIdx.x;
    const int wid = tid >> 5;
    const int lid = tid & 31;
    const int wy  = wid >> 2;
    const int wx  = wid & 3;

    const __nv_bfloat16* vb = g_vb + (size_t)m * CC * NN;
    const __nv_bfloat16* am = g_attn_bf + (size_t)m * NN * NN;
    const uint32_t sbase = smem_u32(smc);

    const int a_row0 = tid >> 1;
    const int a_seg0 = (tid & 1) * 2;
    const int b_row  = tid >> 4;
    const int b_seg  = tid & 15;

    auto prefetch = [&](int c) {
        const int k0 = c * 32;
        const uint32_t st = sbase + (c & 1) * STAGE_BYTES;
        cp16(st + a_row0 * 80 + a_seg0 * 16,
             vb + (size_t)(c0 + a_row0) * NN + k0 + a_seg0 * 8);
        cp16(st + a_row0 * 80 + (a_seg0 + 1) * 16,
             vb + (size_t)(c0 + a_row0) * NN + k0 + (a_seg0 + 1) * 8);
        const uint32_t bb = st + A_BYTES;
        cp16(bb + b_row * 272 + b_seg * 16,
             am + (size_t)(k0 + b_row) * NN + j0 + b_seg * 8);
        cp16(bb + (b_row + 16) * 272 + b_seg * 16,
             am + (size_t)(k0 + b_row + 16) * NN + j0 + b_seg * 8);
        CP_COMMIT();
    };

    wmma::fragment<wmma::accumulator, 16, 16, 16, float> acc[4][2];
    #pragma unroll
    for (int i = 0; i < 4; i++)
        #pragma unroll
        for (int j = 0; j < 2; j++) wmma::fill_fragment(acc[i][j], 0.0f);

    prefetch(0);
    for (int c = 0; c < 32; c++) {
        if (c < 31) { prefetch(c + 1); CP_WAIT(1); }
        else        { CP_WAIT(0); }
        __syncthreads();

        const __nv_bfloat16* As =
            (const __nv_bfloat16*)(smc + (c & 1) * STAGE_BYTES);
        const __nv_bfloat16* Bs =
            (const __nv_bfloat16*)(smc + (c & 1) * STAGE_BYTES + A_BYTES);

        #pragma unroll
        for (int kk = 0; kk < 2; kk++) {
            wmma::fragment<wmma::matrix_a, 16, 16, 16, __nv_bfloat16,
                           wmma::row_major> af[4];
            wmma::fragment<wmma::matrix_b, 16, 16, 16, __nv_bfloat16,
                           wmma::row_major> bf[2];
            #pragma unroll
            for (int i = 0; i < 4; i++)
                wmma::load_matrix_sync(af[i],
                    &As[(wy * 64 + i * 16) * A_LD + kk * 16], A_LD);
            #pragma unroll
            for (int j = 0; j < 2; j++)
                wmma::load_matrix_sync(bf[j],
                    &Bs[kk * 16 * B_LD + wx * 32 + j * 16], B_LD);
            #pragma unroll
            for (int i = 0; i < 4; i++)
                #pragma unroll
                for (int j = 0; j < 2; j++)
                    wmma::mma_sync(acc[i][j], af[i], bf[j], acc[i][j]);
        }
        __syncthreads();
    }

    float* ws = smf + wid * (64 * SCR_LD);
    #pragma unroll
    for (int i = 0; i < 4; i++)
        #pragma unroll
        for (int j = 0; j < 2; j++)
            wmma::store_matrix_sync(&ws[(i * 16) * SCR_LD + j * 16],
                                    acc[i][j], SCR_LD, wmma::mem_row_major);
    __syncwarp();

    const float g = *gp;
    const int rbase = c0 + wy * 64;
    const int cbase = j0 + wx * 32;
    const float* xm = x + (size_t)m * CC * NN;
    float* om = out + (size_t)m * CC * NN;
    #pragma unroll
    for (int it = 0; it < 16; it++) {
        int r  = it * 4 + (lid >> 3);
        int c4 = lid & 7;
        float4 a  = *(const float4*)&ws[r * SCR_LD + c4 * 4];
        const float* xrow = xm + (size_t)(rbase + r) * NN + cbase;
        float4 xv = *(const float4*)&xrow[c4 * 4];
        float4 o;
        o.x = g * a.x + xv.x;
        o.y = g * a.y + xv.y;
        o.z = g * a.z + xv.z;
        o.w = g * a.w + xv.w;
        *(float4*)&om[(size_t)(rbase + r) * NN + cbase + c4 * 4] = o;
    }
}

// ---------------------------------------------------------------------------
extern "C" void kernel_launch(void* const* d_in, const int* in_sizes, int n_in,
                              void* d_out, int out_size)
{
    const float* x     = (const float*)d_in[0];
    const float* wq    = (const float*)d_in[1];
    const float* bq    = (const float*)d_in[2];
    const float* wk    = (const float*)d_in[3];
    const float* bk    = (const float*)d_in[4];
    const float* wv    = (const float*)d_in[5];
    const float* bv    = (const float*)d_in[6];
    const float* gamma = (const float*)d_in[7];
    float* out = (float*)d_out;

    cudaFuncSetAttribute(k_qkv_wmma,
                         cudaFuncAttributeMaxDynamicSharedMemorySize, SMEM_K1);
    cudaFuncSetAttribute(k_attn_wmma,
                         cudaFuncAttributeMaxDynamicSharedMemorySize, SMEM_K2);
    cudaFuncSetAttribute(k_out_wmma,
                         cudaFuncAttributeMaxDynamicSharedMemorySize, SMEM_K3);

    dim3 g1(NN / 128, RR / 64, MB);
    k_qkv_wmma<<<g1, 256, SMEM_K1>>>(x, wq, bq, wk, bk, wv, bv);

    dim3 g2(NN / 128, MB);
    k_attn_wmma<<<g2, 256, SMEM_K2>>>();

    dim3 g3(NN / 128, CC / 128, MB);
    k_out_wmma<<<g3, 256, SMEM_K3>>>(x, gamma, out);
}